// round 1
// baseline (speedup 1.0000x reference)
#include <cuda_runtime.h>

#define BB 4
#define SS_DIM 1024
#define XX 1024
#define CC 8
#define DD 2
#define WIDTH 16
#define DEPTH 4
#define SCHUNK 32
#define TPB 256

// Weights in constant memory (uniform across threads -> LDCU path).
// 64-bit typed storage for the paired loads so ptxas keeps them in const space.
__constant__ float              c_Win[WIDTH];
__constant__ float              c_bin[WIDTH];
__constant__ unsigned long long c_Whid2[DEPTH][WIDTH][WIDTH / 2]; // bitwise = float[4][16][16]
__constant__ unsigned long long c_bhid2[DEPTH][WIDTH / 2];        // bitwise = float[4][16]
__constant__ float              c_Wout[WIDTH];
__constant__ float              c_bout[1];

__device__ __forceinline__ unsigned long long fma2(unsigned long long a,
                                                   unsigned long long b,
                                                   unsigned long long c) {
    unsigned long long d;
    asm("fma.rn.f32x2 %0, %1, %2, %3;" : "=l"(d) : "l"(a), "l"(b), "l"(c));
    return d;
}

__device__ __forceinline__ unsigned long long dup2(float a) {
    unsigned long long r;
    unsigned ai = __float_as_uint(a);
    asm("mov.b64 %0, {%1, %1};" : "=l"(r) : "r"(ai));
    return r;
}

__device__ __forceinline__ void unpack2(unsigned long long v, float& a, float& b) {
    unsigned x, y;
    asm("mov.b64 {%0, %1}, %2;" : "=r"(x), "=r"(y) : "l"(v));
    a = __uint_as_float(x);
    b = __uint_as_float(y);
}

__device__ __forceinline__ float fast_tanh(float x) {
    float y;
    asm("tanh.approx.f32 %0, %1;" : "=f"(y) : "f"(x));
    return y;
}

__global__ __launch_bounds__(TPB)
void ccl_kernel(const float* __restrict__ yu,
                const float* __restrict__ xin,
                float* __restrict__ out) {
    __shared__ float s_y[SCHUNK][DD];
    __shared__ float s_u[SCHUNK][CC];

    const int b  = blockIdx.z;
    const int s0 = blockIdx.y * SCHUNK;
    const int xi = blockIdx.x * TPB + threadIdx.x;

    // Stage this block's yu chunk: SCHUNK rows x 10 floats.
    for (int i = threadIdx.x; i < SCHUNK * (CC + DD); i += TPB) {
        const int s = i / (CC + DD);
        const int c = i % (CC + DD);
        const float v = yu[((size_t)b * SS_DIM + (s0 + s)) * (CC + DD) + c];
        if (c < CC) s_u[s][c] = v;
        else        s_y[s][c - CC] = v;
    }
    __syncthreads();

    const float2 xv = *reinterpret_cast<const float2*>(&xin[((size_t)b * XX + xi) * DD]);

    float acc[CC];
#pragma unroll
    for (int c = 0; c < CC; ++c) acc[c] = 0.0f;

#pragma unroll 1
    for (int ss = 0; ss < SCHUNK; ++ss) {
        const float d0 = xv.x - s_y[ss][0];
        const float d1 = xv.y - s_y[ss][1];
        const float r  = d0 * d0 + d1 * d1;

        float h[WIDTH];
#pragma unroll
        for (int j = 0; j < WIDTH; ++j) h[j] = fmaf(r, c_Win[j], c_bin[j]);

#pragma unroll
        for (int l = 0; l < DEPTH; ++l) {
            unsigned long long z2[WIDTH / 2];
#pragma unroll
            for (int jp = 0; jp < WIDTH / 2; ++jp) z2[jp] = c_bhid2[l][jp];
#pragma unroll
            for (int kk = 0; kk < WIDTH; ++kk) {
                const unsigned long long hk2 = dup2(h[kk]);
#pragma unroll
                for (int jp = 0; jp < WIDTH / 2; ++jp)
                    z2[jp] = fma2(hk2, c_Whid2[l][kk][jp], z2[jp]);
            }
#pragma unroll
            for (int jp = 0; jp < WIDTH / 2; ++jp) {
                float za, zb;
                unpack2(z2[jp], za, zb);
                h[2 * jp]     += fast_tanh(za);
                h[2 * jp + 1] += fast_tanh(zb);
            }
        }

        float k = c_bout[0];
#pragma unroll
        for (int j = 0; j < WIDTH; ++j) k = fmaf(h[j], c_Wout[j], k);

#pragma unroll
        for (int c = 0; c < CC; ++c) acc[c] = fmaf(k, s_u[ss][c], acc[c]);
    }

    const float invS = 1.0f / (float)SS_DIM;
    float* op = &out[((size_t)b * XX + xi) * CC];
#pragma unroll
    for (int c = 0; c < CC; ++c) atomicAdd(&op[c], acc[c] * invS);
}

extern "C" void kernel_launch(void* const* d_in, const int* in_sizes, int n_in,
                              void* d_out, int out_size) {
    const float* yu    = (const float*)d_in[0]; // (4,1024,10)
    const float* x     = (const float*)d_in[1]; // (4,1024,2)
    const float* W_in  = (const float*)d_in[2]; // (1,16)
    const float* b_in  = (const float*)d_in[3]; // (16,)
    const float* W_hid = (const float*)d_in[4]; // (4,16,16)
    const float* b_hid = (const float*)d_in[5]; // (4,16)
    const float* W_out = (const float*)d_in[6]; // (16,1)
    const float* b_out = (const float*)d_in[7]; // (1,)

    (void)in_sizes; (void)n_in;

    cudaMemcpyToSymbolAsync(c_Win,   W_in,  WIDTH * sizeof(float), 0, cudaMemcpyDeviceToDevice, 0);
    cudaMemcpyToSymbolAsync(c_bin,   b_in,  WIDTH * sizeof(float), 0, cudaMemcpyDeviceToDevice, 0);
    cudaMemcpyToSymbolAsync(c_Whid2, W_hid, DEPTH * WIDTH * WIDTH * sizeof(float), 0, cudaMemcpyDeviceToDevice, 0);
    cudaMemcpyToSymbolAsync(c_bhid2, b_hid, DEPTH * WIDTH * sizeof(float), 0, cudaMemcpyDeviceToDevice, 0);
    cudaMemcpyToSymbolAsync(c_Wout,  W_out, WIDTH * sizeof(float), 0, cudaMemcpyDeviceToDevice, 0);
    cudaMemcpyToSymbolAsync(c_bout,  b_out, 1 * sizeof(float), 0, cudaMemcpyDeviceToDevice, 0);

    cudaMemsetAsync(d_out, 0, (size_t)out_size * sizeof(float), 0);

    dim3 grid(XX / TPB, SS_DIM / SCHUNK, BB);
    ccl_kernel<<<grid, TPB, 0, 0>>>(yu, x, (float*)d_out);
}